// round 8
// baseline (speedup 1.0000x reference)
#include <cuda_runtime.h>

// ctrl_pts: (16,64,64,4) f32 | uspan/vspan: (512,) i32 | Nu/Nv: (512,4) f32
// out: (16,512,512,3) f32
#define BATCH   16
#define MCTRL   64
#define NCTRL   64
#define OUTN    512
#define PDEG    3
#define NB      4          // batches per block

typedef unsigned long long ull;

__device__ __forceinline__ ull pack2(float a, float b) {
    ull r; asm("mov.b64 %0, {%1,%2};" : "=l"(r) : "f"(a), "f"(b)); return r;
}
__device__ __forceinline__ void unpack2(ull v, float& a, float& b) {
    asm("mov.b64 {%0,%1}, %2;" : "=f"(a), "=f"(b) : "l"(v));
}
__device__ __forceinline__ ull mul2(ull a, ull b) {
    ull d; asm("mul.rn.f32x2 %0, %1, %2;" : "=l"(d) : "l"(a), "l"(b)); return d;
}
__device__ __forceinline__ ull fma2(ull a, ull b, ull c) {
    ull d; asm("fma.rn.f32x2 %0, %1, %2, %3;" : "=l"(d) : "l"(a), "l"(b), "l"(c)); return d;
}
__device__ __forceinline__ float rcp_approx(float x) {
    float r; asm("rcp.approx.f32 %0, %1;" : "=f"(r) : "f"(x)); return r;
}
__device__ __forceinline__ void prefetch_l1(const void* p) {
    asm volatile("prefetch.global.L1 [%0];" :: "l"(p));
}

// ---------------------------------------------------------------------------
// Fused kernel with batch loop. Block = (u-tile of 4 rows) x (4 batches).
// 256 threads, 4 blocks/SM. Weights + u-setup amortized over NB batches;
// sA double-buffered (1 barrier per batch); next batch's ctrl rows
// prefetched into L1 during current phase 2.
// ---------------------------------------------------------------------------
__global__ __launch_bounds__(256, 4)
void surf_fused(const float4* __restrict__ ctrl,
                const int*    __restrict__ uspan,
                const int2*   __restrict__ vspan2,
                const float4* __restrict__ Nu4,
                const float4* __restrict__ Nv4,
                float2*       __restrict__ out)
{
    __shared__ float4 sA[2][4 * NCTRL];       // 8 KB double buffer

    int t  = threadIdx.x;                     // 0..255
    int u0 = blockIdx.x * 4;
    int b0 = blockIdx.y * NB;

    // ---- loop-invariant phase-1 setup (per-thread (ul, n) mapping) ----
    int n  = t & (NCTRL - 1);
    int ul = t >> 6;                          // 0..3
    int u  = u0 + ul;
    int iu0 = __ldg(uspan + u) - PDEG;
    float4 nu = __ldg(Nu4 + u);
    const float4* base = ctrl + (((b0 * MCTRL) + iu0) * NCTRL + n);

    // ---- loop-invariant phase-2 weight setup (v-pair 2g, 2g+1) ----
    int g = t;
    int2 vs  = __ldg(vspan2 + g);
    int  iv0 = vs.x - PDEG;
    bool sh  = vs.y != vs.x;

    ull wp[2][5];
    {
        float4 nv0 = __ldg(Nv4 + 2 * g);
        float4 nv1 = __ldg(Nv4 + 2 * g + 1);
        wp[0][0] = pack2(nv0.x, nv0.x);
        wp[0][1] = pack2(nv0.y, nv0.y);
        wp[0][2] = pack2(nv0.z, nv0.z);
        wp[0][3] = pack2(nv0.w, nv0.w);
        wp[0][4] = pack2(0.0f, 0.0f);
        float w0 = sh ? 0.0f : nv1.x;
        float w1 = sh ? nv1.x : nv1.y;
        float w2 = sh ? nv1.y : nv1.z;
        float w3 = sh ? nv1.z : nv1.w;
        float w4 = sh ? nv1.w : 0.0f;
        wp[1][0] = pack2(w0, w0);
        wp[1][1] = pack2(w1, w1);
        wp[1][2] = pack2(w2, w2);
        wp[1][3] = pack2(w3, w3);
        wp[1][4] = pack2(w4, w4);
    }

#pragma unroll
    for (int bb = 0; bb < NB; bb++) {
        int b = b0 + bb;

        // ---------------- Phase 1: one A entry per thread ----------------
        {
            float4 c0 = __ldg(base + 0 * NCTRL);
            float4 c1 = __ldg(base + 1 * NCTRL);
            float4 c2 = __ldg(base + 2 * NCTRL);
            float4 c3 = __ldg(base + 3 * NCTRL);

            float4 acc;
            acc.x = nu.x*c0.x + nu.y*c1.x + nu.z*c2.x + nu.w*c3.x;
            acc.y = nu.x*c0.y + nu.y*c1.y + nu.z*c2.y + nu.w*c3.y;
            acc.z = nu.x*c0.z + nu.y*c1.z + nu.z*c2.z + nu.w*c3.z;
            acc.w = nu.x*c0.w + nu.y*c1.w + nu.z*c2.w + nu.w*c3.w;

            sA[bb & 1][ul * NCTRL + n] = acc;
        }

        // Prefetch next batch's ctrl rows into L1 (hidden under phase 2).
        base += MCTRL * NCTRL;
        if (bb < NB - 1) {
            prefetch_l1(base + 0 * NCTRL);
            prefetch_l1(base + 1 * NCTRL);
            prefetch_l1(base + 2 * NCTRL);
            prefetch_l1(base + 3 * NCTRL);
        }

        __syncthreads();

        // ---------------- Phase 2: v-pair over 4 rows ----------------
        const float4* __restrict__ buf = sA[bb & 1];

#pragma unroll
        for (int i = 0; i < 4; i++) {
            const ulonglong2* __restrict__ Ab =
                (const ulonglong2*)(buf + i * NCTRL + iv0);
            ulonglong2 a0 = Ab[0];
            ulonglong2 a1 = Ab[1];
            ulonglong2 a2 = Ab[2];
            ulonglong2 a3 = Ab[3];
            ulonglong2 a4 = Ab[4];

            float res[6];
#pragma unroll
            for (int k = 0; k < 2; k++) {
                ull axy = mul2(wp[k][0], a0.x);
                ull azw = mul2(wp[k][0], a0.y);
                axy = fma2(wp[k][1], a1.x, axy);
                azw = fma2(wp[k][1], a1.y, azw);
                axy = fma2(wp[k][2], a2.x, axy);
                azw = fma2(wp[k][2], a2.y, azw);
                axy = fma2(wp[k][3], a3.x, axy);
                azw = fma2(wp[k][3], a3.y, azw);
                axy = fma2(wp[k][4], a4.x, axy);
                azw = fma2(wp[k][4], a4.y, azw);

                float sx, sy, sz, sw;
                unpack2(axy, sx, sy);
                unpack2(azw, sz, sw);
                float inv = rcp_approx(sw);
                res[k * 3 + 0] = sx * inv;
                res[k * 3 + 1] = sy * inv;
                res[k * 3 + 2] = sz * inv;
            }

            float2* __restrict__ o =
                out + (size_t)(b * OUTN + (u0 + i)) * (OUTN * 3 / 2) + 3 * g;
            o[0] = make_float2(res[0], res[1]);
            o[1] = make_float2(res[2], res[3]);
            o[2] = make_float2(res[4], res[5]);
        }
    }
}

extern "C" void kernel_launch(void* const* d_in, const int* in_sizes, int n_in,
                              void* d_out, int out_size)
{
    const float4* ctrl   = (const float4*)d_in[0];
    const int*    uspan  = (const int*)   d_in[1];
    const int2*   vspan2 = (const int2*)  d_in[2];
    const float4* Nu4    = (const float4*)d_in[3];
    const float4* Nv4    = (const float4*)d_in[4];
    float2*       out    = (float2*)      d_out;

    dim3 grid(OUTN / 4, BATCH / NB);          // 128 x 4 = 512 blocks
    surf_fused<<<grid, 256>>>(ctrl, uspan, vspan2, Nu4, Nv4, out);
}

// round 9
// speedup vs baseline: 1.4374x; 1.4374x over previous
#include <cuda_runtime.h>

// ctrl_pts: (16,64,64,4) f32 | uspan/vspan: (512,) i32 | Nu/Nv: (512,4) f32
// out: (16,512,512,3) f32
#define BATCH   16
#define MCTRL   64
#define NCTRL   64
#define OUTN    512
#define PDEG    3

typedef unsigned long long ull;

__device__ __forceinline__ ull pack2(float a, float b) {
    ull r; asm("mov.b64 %0, {%1,%2};" : "=l"(r) : "f"(a), "f"(b)); return r;
}
__device__ __forceinline__ void unpack2(ull v, float& a, float& b) {
    asm("mov.b64 {%0,%1}, %2;" : "=f"(a), "=f"(b) : "l"(v));
}
__device__ __forceinline__ ull mul2(ull a, ull b) {
    ull d; asm("mul.rn.f32x2 %0, %1, %2;" : "=l"(d) : "l"(a), "l"(b)); return d;
}
__device__ __forceinline__ ull fma2(ull a, ull b, ull c) {
    ull d; asm("fma.rn.f32x2 %0, %1, %2, %3;" : "=l"(d) : "l"(a), "l"(b), "l"(c)); return d;
}
__device__ __forceinline__ float rcp_approx(float x) {
    float r; asm("rcp.approx.f32 %0, %1;" : "=f"(r) : "f"(x)); return r;
}

// ---------------------------------------------------------------------------
// Fused kernel. Block = (b, 4 u-rows), 256 threads, 4 blocks/SM.
// Phase 1: A[4][64] into smem — one entry per thread.
// Phase 2: thread g owns v-pair (2g, 2g+1); weights expanded once into a
//          f32x2-packed 5-window, reused over 4 rows.
// Stores:  warp-private smem transpose -> contiguous STG.128 (full 32B
//          sectors; kills the 3x L2 partial-sector write amplification).
// ---------------------------------------------------------------------------
__global__ __launch_bounds__(256, 4)
void surf_fused(const float4* __restrict__ ctrl,
                const int*    __restrict__ uspan,
                const int2*   __restrict__ vspan2,
                const float4* __restrict__ Nu4,
                const float4* __restrict__ Nv4,
                float4*       __restrict__ out4)
{
    __shared__ float4 sA[4 * NCTRL];                     // 4 KB
    __shared__ __align__(16) float2 sOut[8][96];         // 8 warps x 768 B

    int t  = threadIdx.x;                     // 0..255
    int b  = blockIdx.y;
    int u0 = blockIdx.x * 4;
    int lane = t & 31;
    int wrp  = t >> 5;

    // ---------------- Phase 1: one A entry per thread ----------------
    {
        int n  = t & (NCTRL - 1);
        int ul = t >> 6;                      // 0..3
        int u  = u0 + ul;
        int iu0 = __ldg(uspan + u) - PDEG;
        const float4* __restrict__ base =
            ctrl + ((b * MCTRL + iu0) * NCTRL + n);
        float4 c0 = __ldg(base + 0 * NCTRL);
        float4 c1 = __ldg(base + 1 * NCTRL);
        float4 c2 = __ldg(base + 2 * NCTRL);
        float4 c3 = __ldg(base + 3 * NCTRL);
        float4 nu = __ldg(Nu4 + u);

        float4 acc;
        acc.x = nu.x*c0.x + nu.y*c1.x + nu.z*c2.x + nu.w*c3.x;
        acc.y = nu.x*c0.y + nu.y*c1.y + nu.z*c2.y + nu.w*c3.y;
        acc.z = nu.x*c0.z + nu.y*c1.z + nu.z*c2.z + nu.w*c3.z;
        acc.w = nu.x*c0.w + nu.y*c1.w + nu.z*c2.w + nu.w*c3.w;

        sA[ul * NCTRL + n] = acc;
    }
    __syncthreads();

    // ---------------- Phase 2: v-pair (2g, 2g+1), 4 rows ----------------
    int g = t;
    int2 vs  = __ldg(vspan2 + g);
    int  iv0 = vs.x - PDEG;
    bool sh  = vs.y != vs.x;

    ull wp[2][5];
    {
        float4 nv0 = __ldg(Nv4 + 2 * g);
        float4 nv1 = __ldg(Nv4 + 2 * g + 1);
        wp[0][0] = pack2(nv0.x, nv0.x);
        wp[0][1] = pack2(nv0.y, nv0.y);
        wp[0][2] = pack2(nv0.z, nv0.z);
        wp[0][3] = pack2(nv0.w, nv0.w);
        wp[0][4] = pack2(0.0f, 0.0f);
        float w0 = sh ? 0.0f : nv1.x;
        float w1 = sh ? nv1.x : nv1.y;
        float w2 = sh ? nv1.y : nv1.z;
        float w3 = sh ? nv1.z : nv1.w;
        float w4 = sh ? nv1.w : 0.0f;
        wp[1][0] = pack2(w0, w0);
        wp[1][1] = pack2(w1, w1);
        wp[1][2] = pack2(w2, w2);
        wp[1][3] = pack2(w3, w3);
        wp[1][4] = pack2(w4, w4);
    }

    float2* __restrict__ sb  = sOut[wrp];
    const float4* __restrict__ sb4 = (const float4*)sOut[wrp];

#pragma unroll
    for (int i = 0; i < 4; i++) {
        int u = u0 + i;

        const ulonglong2* __restrict__ Ab =
            (const ulonglong2*)(sA + i * NCTRL + iv0);
        ulonglong2 a0 = Ab[0];
        ulonglong2 a1 = Ab[1];
        ulonglong2 a2 = Ab[2];
        ulonglong2 a3 = Ab[3];
        ulonglong2 a4 = Ab[4];

        float res[6];
#pragma unroll
        for (int k = 0; k < 2; k++) {
            ull axy = mul2(wp[k][0], a0.x);
            ull azw = mul2(wp[k][0], a0.y);
            axy = fma2(wp[k][1], a1.x, axy);
            azw = fma2(wp[k][1], a1.y, azw);
            axy = fma2(wp[k][2], a2.x, axy);
            azw = fma2(wp[k][2], a2.y, azw);
            axy = fma2(wp[k][3], a3.x, axy);
            azw = fma2(wp[k][3], a3.y, azw);
            axy = fma2(wp[k][4], a4.x, axy);
            azw = fma2(wp[k][4], a4.y, azw);

            float sx, sy, sz, sw;
            unpack2(axy, sx, sy);
            unpack2(azw, sz, sw);
            float inv = rcp_approx(sw);
            res[k * 3 + 0] = sx * inv;
            res[k * 3 + 1] = sy * inv;
            res[k * 3 + 2] = sz * inv;
        }

        // Stage this warp's 64 points (768 B) in smem, then write coalesced.
        sb[3 * lane + 0] = make_float2(res[0], res[1]);
        sb[3 * lane + 1] = make_float2(res[2], res[3]);
        sb[3 * lane + 2] = make_float2(res[4], res[5]);
        __syncwarp();

        // Warp's chunk: 48 float4 at row offset wrp*48.
        float4* __restrict__ orow =
            out4 + (size_t)(b * OUTN + u) * (OUTN * 3 / 4) + wrp * 48;
        orow[lane] = sb4[lane];
        if (lane < 16)
            orow[32 + lane] = sb4[32 + lane];
        __syncwarp();
    }
}

extern "C" void kernel_launch(void* const* d_in, const int* in_sizes, int n_in,
                              void* d_out, int out_size)
{
    const float4* ctrl   = (const float4*)d_in[0];
    const int*    uspan  = (const int*)   d_in[1];
    const int2*   vspan2 = (const int2*)  d_in[2];
    const float4* Nu4    = (const float4*)d_in[3];
    const float4* Nv4    = (const float4*)d_in[4];
    float4*       out4   = (float4*)      d_out;

    dim3 grid(OUTN / 4, BATCH);               // 128 x 16 = 2048 blocks
    surf_fused<<<grid, 256>>>(ctrl, uspan, vspan2, Nu4, Nv4, out4);
}

// round 10
// speedup vs baseline: 1.4592x; 1.0152x over previous
#include <cuda_runtime.h>

// ctrl_pts: (16,64,64,4) f32 | uspan/vspan: (512,) i32 | Nu/Nv: (512,4) f32
// out: (16,512,512,3) f32
#define BATCH   16
#define MCTRL   64
#define NCTRL   64
#define OUTN    512
#define PDEG    3

typedef unsigned long long ull;

__device__ __forceinline__ ull pack2(float a, float b) {
    ull r; asm("mov.b64 %0, {%1,%2};" : "=l"(r) : "f"(a), "f"(b)); return r;
}
__device__ __forceinline__ void unpack2(ull v, float& a, float& b) {
    asm("mov.b64 {%0,%1}, %2;" : "=f"(a), "=f"(b) : "l"(v));
}
__device__ __forceinline__ ull mul2(ull a, ull b) {
    ull d; asm("mul.rn.f32x2 %0, %1, %2;" : "=l"(d) : "l"(a), "l"(b)); return d;
}
__device__ __forceinline__ ull fma2(ull a, ull b, ull c) {
    ull d; asm("fma.rn.f32x2 %0, %1, %2, %3;" : "=l"(d) : "l"(a), "l"(b), "l"(c)); return d;
}
__device__ __forceinline__ float rcp_approx(float x) {
    float r; asm("rcp.approx.f32 %0, %1;" : "=f"(r) : "f"(x)); return r;
}

// ---------------------------------------------------------------------------
// Fused kernel. Block = (b, 4 u-rows), 256 threads, 5 blocks/SM.
// Weight setup hoisted ABOVE phase 1 so its cold loads overlap ctrl loads.
// Phase 1: A[4][64] into smem — one entry per thread.
// Phase 2: thread g owns v-pair (2g, 2g+1); f32x2 5-window weights reused
//          over 4 rows. Stores staged through double-buffered warp-private
//          smem -> contiguous STG.128 (full 32B sectors).
// ---------------------------------------------------------------------------
__global__ __launch_bounds__(256, 5)
void surf_fused(const float4* __restrict__ ctrl,
                const int*    __restrict__ uspan,
                const int2*   __restrict__ vspan2,
                const float4* __restrict__ Nu4,
                const float4* __restrict__ Nv4,
                float4*       __restrict__ out4)
{
    __shared__ float4 sA[4 * NCTRL];                     // 4 KB
    __shared__ __align__(16) float2 sOut[2][8][96];      // 2 x 8 warps x 768 B

    int t  = threadIdx.x;                     // 0..255
    int b  = blockIdx.y;
    int u0 = blockIdx.x * 4;
    int lane = t & 31;
    int wrp  = t >> 5;

    // ---- phase-2 weight setup (hoisted: overlaps phase-1 LDGs) ----
    int g = t;
    int2 vs  = __ldg(vspan2 + g);
    int  iv0 = vs.x - PDEG;
    bool sh  = vs.y != vs.x;

    ull wp[2][5];
    {
        float4 nv0 = __ldg(Nv4 + 2 * g);
        float4 nv1 = __ldg(Nv4 + 2 * g + 1);
        wp[0][0] = pack2(nv0.x, nv0.x);
        wp[0][1] = pack2(nv0.y, nv0.y);
        wp[0][2] = pack2(nv0.z, nv0.z);
        wp[0][3] = pack2(nv0.w, nv0.w);
        wp[0][4] = pack2(0.0f, 0.0f);
        float w0 = sh ? 0.0f : nv1.x;
        float w1 = sh ? nv1.x : nv1.y;
        float w2 = sh ? nv1.y : nv1.z;
        float w3 = sh ? nv1.z : nv1.w;
        float w4 = sh ? nv1.w : 0.0f;
        wp[1][0] = pack2(w0, w0);
        wp[1][1] = pack2(w1, w1);
        wp[1][2] = pack2(w2, w2);
        wp[1][3] = pack2(w3, w3);
        wp[1][4] = pack2(w4, w4);
    }

    // ---------------- Phase 1: one A entry per thread ----------------
    {
        int n  = t & (NCTRL - 1);
        int ul = t >> 6;                      // 0..3
        int u  = u0 + ul;
        int iu0 = __ldg(uspan + u) - PDEG;
        const float4* __restrict__ base =
            ctrl + ((b * MCTRL + iu0) * NCTRL + n);
        float4 c0 = __ldg(base + 0 * NCTRL);
        float4 c1 = __ldg(base + 1 * NCTRL);
        float4 c2 = __ldg(base + 2 * NCTRL);
        float4 c3 = __ldg(base + 3 * NCTRL);
        float4 nu = __ldg(Nu4 + u);

        float4 acc;
        acc.x = nu.x*c0.x + nu.y*c1.x + nu.z*c2.x + nu.w*c3.x;
        acc.y = nu.x*c0.y + nu.y*c1.y + nu.z*c2.y + nu.w*c3.y;
        acc.z = nu.x*c0.z + nu.y*c1.z + nu.z*c2.z + nu.w*c3.z;
        acc.w = nu.x*c0.w + nu.y*c1.w + nu.z*c2.w + nu.w*c3.w;

        sA[ul * NCTRL + n] = acc;
    }
    __syncthreads();

    // ---------------- Phase 2: v-pair (2g, 2g+1), 4 rows ----------------
#pragma unroll
    for (int i = 0; i < 4; i++) {
        int u = u0 + i;

        const ulonglong2* __restrict__ Ab =
            (const ulonglong2*)(sA + i * NCTRL + iv0);
        ulonglong2 a0 = Ab[0];
        ulonglong2 a1 = Ab[1];
        ulonglong2 a2 = Ab[2];
        ulonglong2 a3 = Ab[3];
        ulonglong2 a4 = Ab[4];

        float res[6];
#pragma unroll
        for (int k = 0; k < 2; k++) {
            ull axy = mul2(wp[k][0], a0.x);
            ull azw = mul2(wp[k][0], a0.y);
            axy = fma2(wp[k][1], a1.x, axy);
            azw = fma2(wp[k][1], a1.y, azw);
            axy = fma2(wp[k][2], a2.x, axy);
            azw = fma2(wp[k][2], a2.y, azw);
            axy = fma2(wp[k][3], a3.x, axy);
            azw = fma2(wp[k][3], a3.y, azw);
            axy = fma2(wp[k][4], a4.x, axy);
            azw = fma2(wp[k][4], a4.y, azw);

            float sx, sy, sz, sw;
            unpack2(axy, sx, sy);
            unpack2(azw, sz, sw);
            float inv = rcp_approx(sw);
            res[k * 3 + 0] = sx * inv;
            res[k * 3 + 1] = sy * inv;
            res[k * 3 + 2] = sz * inv;
        }

        // Stage 64 points (768 B) in this warp's buffer (double-buffered),
        // then write out as contiguous 16B chunks.
        float2* __restrict__ sb = sOut[i & 1][wrp];
        sb[3 * lane + 0] = make_float2(res[0], res[1]);
        sb[3 * lane + 1] = make_float2(res[2], res[3]);
        sb[3 * lane + 2] = make_float2(res[4], res[5]);
        __syncwarp();

        const float4* __restrict__ sb4 = (const float4*)sb;
        float4* __restrict__ orow =
            out4 + (size_t)(b * OUTN + u) * (OUTN * 3 / 4) + wrp * 48;
        orow[lane] = sb4[lane];
        if (lane < 16)
            orow[32 + lane] = sb4[32 + lane];
        // no trailing __syncwarp: next iter uses the other buffer
    }
}

extern "C" void kernel_launch(void* const* d_in, const int* in_sizes, int n_in,
                              void* d_out, int out_size)
{
    const float4* ctrl   = (const float4*)d_in[0];
    const int*    uspan  = (const int*)   d_in[1];
    const int2*   vspan2 = (const int2*)  d_in[2];
    const float4* Nu4    = (const float4*)d_in[3];
    const float4* Nv4    = (const float4*)d_in[4];
    float4*       out4   = (float4*)      d_out;

    dim3 grid(OUTN / 4, BATCH);               // 128 x 16 = 2048 blocks
    surf_fused<<<grid, 256>>>(ctrl, uspan, vspan2, Nu4, Nv4, out4);
}